// round 10
// baseline (speedup 1.0000x reference)
#include <cuda_runtime.h>
#include <cuda_bf16.h>
#include <cstdint>

// SVD recommender predict:
//   predict[b]  = clip(gm + bu[uid] + bi[iid] + dot(pu[uid], qi[iid]), 1, 5)
//   feat[b,:64] = pu[uid], feat[b,64:128] = qi[iid]
// d_out layout: [0:B) predict, [B : B+B*128) features row-major.
//
// 4 lanes/element. Each lane: 2x 256-bit evict_last gathers from pu row +
// 2x from qi row (sm_103 requires .v8.b32 for L2::evict_last). Unique row
// set (~59MB) pins in 126MB L2 across graph replays; 67MB output stream
// uses .cs evict-first stores so it can't displace the pinned lines.

#define N_FACTORS 64
#define BATCH     131072

struct f8 { float v[8]; };

__device__ __forceinline__ f8 ldg_el8(const void* p) {
    f8 r;
    asm("ld.global.nc.L2::evict_last.v8.b32 {%0,%1,%2,%3,%4,%5,%6,%7}, [%8];"
        : "=f"(r.v[0]), "=f"(r.v[1]), "=f"(r.v[2]), "=f"(r.v[3]),
          "=f"(r.v[4]), "=f"(r.v[5]), "=f"(r.v[6]), "=f"(r.v[7])
        : "l"(p));
    return r;
}
__device__ __forceinline__ void stcs4(float4* p, float a, float b, float c, float d) {
    asm volatile("st.global.cs.v4.f32 [%0], {%1,%2,%3,%4};"
                 :: "l"(p), "f"(a), "f"(b), "f"(c), "f"(d));
}

__global__ __launch_bounds__(256) void svd_predict_kernel(
    const int2*  __restrict__ user_item,   // [BATCH] (uid, iid)
    const char*  __restrict__ pu,          // rows of 256B
    const char*  __restrict__ qi,
    const float* __restrict__ bu,
    const float* __restrict__ bi,
    const float* __restrict__ gmean,
    float*       __restrict__ out_pred,    // [BATCH]
    char*        __restrict__ out_feat)    // [BATCH*512] bytes
{
    const int tid  = blockIdx.x * blockDim.x + threadIdx.x;
    const int elem = tid >> 2;          // batch element
    const int lane = tid & 3;           // lane within 4-lane group
    if (elem >= BATCH) return;

    const int2 ui = user_item[elem];
    const int uid = ui.x;
    const int iid = ui.y;

    const char* prow = pu + (size_t)uid * 256;
    const char* qrow = qi + (size_t)iid * 256;

    // 4 independent 256-bit gathers; lanes cover consecutive 32B chunks.
    // chunk j: byte offset lane*32 + j*128  (j = 0,1)
    f8 p0 = ldg_el8(prow + lane * 32);
    f8 p1 = ldg_el8(prow + lane * 32 + 128);
    f8 q0 = ldg_el8(qrow + lane * 32);
    f8 q1 = ldg_el8(qrow + lane * 32 + 128);

    float dot = 0.0f;
    #pragma unroll
    for (int k = 0; k < 8; k++) dot += p0.v[k] * q0.v[k];
    #pragma unroll
    for (int k = 0; k < 8; k++) dot += p1.v[k] * q1.v[k];
    dot += __shfl_xor_sync(0xffffffffu, dot, 2);
    dot += __shfl_xor_sync(0xffffffffu, dot, 1);

    // Feature row: p at [0,256), q at [256,512). Evict-first streaming stores.
    char* frow = out_feat + (size_t)elem * 512;
    #pragma unroll
    for (int h = 0; h < 2; h++) {
        stcs4((float4*)(frow + lane * 32 + h * 128),
              (h ? p1 : p0).v[0], (h ? p1 : p0).v[1], (h ? p1 : p0).v[2], (h ? p1 : p0).v[3]);
        stcs4((float4*)(frow + lane * 32 + h * 128 + 16),
              (h ? p1 : p0).v[4], (h ? p1 : p0).v[5], (h ? p1 : p0).v[6], (h ? p1 : p0).v[7]);
        stcs4((float4*)(frow + 256 + lane * 32 + h * 128),
              (h ? q1 : q0).v[0], (h ? q1 : q0).v[1], (h ? q1 : q0).v[2], (h ? q1 : q0).v[3]);
        stcs4((float4*)(frow + 256 + lane * 32 + h * 128 + 16),
              (h ? q1 : q0).v[4], (h ? q1 : q0).v[5], (h ? q1 : q0).v[6], (h ? q1 : q0).v[7]);
    }

    if (lane == 0) {
        float pr = gmean[0] + __ldg(bu + uid) + __ldg(bi + iid) + dot;
        pr = fminf(fmaxf(pr, 1.0f), 5.0f);
        __stcs(out_pred + elem, pr);
    }
}

extern "C" void kernel_launch(void* const* d_in, const int* in_sizes, int n_in,
                              void* d_out, int out_size)
{
    const int2*  user_item = (const int2*) d_in[0];
    const char*  pu        = (const char*) d_in[1];
    const char*  qi        = (const char*) d_in[2];
    const float* bu        = (const float*)d_in[3];
    const float* bi        = (const float*)d_in[4];
    const float* gmean     = (const float*)d_in[5];

    float* out_pred = (float*)d_out;
    char*  out_feat = (char*)((float*)d_out + BATCH);

    const int threads = 256;
    const int blocks  = (BATCH * 4) / threads;   // 2048
    svd_predict_kernel<<<blocks, threads>>>(user_item, pu, qi, bu, bi, gmean,
                                            out_pred, out_feat);
}

// round 12
// speedup vs baseline: 1.6829x; 1.6829x over previous
#include <cuda_runtime.h>
#include <cuda_bf16.h>
#include <cstdint>

// SVD recommender predict:
//   predict[b]  = clip(gm + bu[uid] + bi[iid] + dot(pu[uid], qi[iid]), 1, 5)
//   feat[b,:64] = pu[uid], feat[b,64:128] = qi[iid]
// d_out layout: [0:B) predict, [B : B+B*128) features row-major.
//
// Wavefront-optimal layout: 8 lanes per element. Each LDG.128/STG.128 across
// the warp covers 4 distinct rows x one FULL 128B line -> 4 wavefronts/instr,
// zero wasted sectors. Per element: 8 wavefronts total (the minimum for
// 512B in + 512B out). MLP=4 independent gathers per thread.

#define N_FACTORS 64
#define BATCH     131072

__device__ __forceinline__ void stcs4(float4* p, float4 v) {
    asm volatile("st.global.cs.v4.f32 [%0], {%1,%2,%3,%4};"
                 :: "l"(p), "f"(v.x), "f"(v.y), "f"(v.z), "f"(v.w));
}

__global__ __launch_bounds__(256) void svd_predict_kernel(
    const int2*   __restrict__ user_item,   // [BATCH] (uid, iid)
    const float4* __restrict__ pu,          // [N_USERS * 16] float4
    const float4* __restrict__ qi,          // [N_ITEMS * 16] float4
    const float*  __restrict__ bu,
    const float*  __restrict__ bi,
    const float*  __restrict__ gmean,
    float*        __restrict__ out_pred,    // [BATCH]
    float4*       __restrict__ out_feat)    // [BATCH * 32] float4
{
    const int tid  = blockIdx.x * blockDim.x + threadIdx.x;
    const int elem = tid >> 3;          // batch element
    const int lane = tid & 7;           // lane within 8-lane group
    if (elem >= BATCH) return;

    const int2 ui = user_item[elem];
    const int uid = ui.x;
    const int iid = ui.y;

    const float4* __restrict__ prow = pu + (size_t)uid * (N_FACTORS / 4);
    const float4* __restrict__ qrow = qi + (size_t)iid * (N_FACTORS / 4);

    // 4 independent LDG.128 per thread; 8 lanes x 16B = one full 128B line
    // per row per instruction.
    const float4 p0 = __ldg(prow + lane);
    const float4 p1 = __ldg(prow + 8 + lane);
    const float4 q0 = __ldg(qrow + lane);
    const float4 q1 = __ldg(qrow + 8 + lane);

    float dot = p0.x * q0.x + p0.y * q0.y + p0.z * q0.z + p0.w * q0.w
              + p1.x * q1.x + p1.y * q1.y + p1.z * q1.z + p1.w * q1.w;

    // Reduce across the 8-lane group.
    dot += __shfl_xor_sync(0xffffffffu, dot, 4);
    dot += __shfl_xor_sync(0xffffffffu, dot, 2);
    dot += __shfl_xor_sync(0xffffffffu, dot, 1);

    // Feature row: 128 floats = 32 float4; same full-line geometry on stores.
    float4* frow = out_feat + (size_t)elem * (2 * N_FACTORS / 4);
    stcs4(frow + lane,      p0);
    stcs4(frow + 8 + lane,  p1);
    stcs4(frow + 16 + lane, q0);
    stcs4(frow + 24 + lane, q1);

    if (lane == 0) {
        float pr = gmean[0] + __ldg(bu + uid) + __ldg(bi + iid) + dot;
        pr = fminf(fmaxf(pr, 1.0f), 5.0f);
        __stcs(out_pred + elem, pr);
    }
}

extern "C" void kernel_launch(void* const* d_in, const int* in_sizes, int n_in,
                              void* d_out, int out_size)
{
    const int2*   user_item = (const int2*)  d_in[0];
    const float4* pu        = (const float4*)d_in[1];
    const float4* qi        = (const float4*)d_in[2];
    const float*  bu        = (const float*) d_in[3];
    const float*  bi        = (const float*) d_in[4];
    const float*  gmean     = (const float*) d_in[5];

    float*  out_pred = (float*)d_out;
    float4* out_feat = (float4*)((float*)d_out + BATCH);

    const int threads = 256;
    const int blocks  = (BATCH * 8) / threads;   // 4096
    svd_predict_kernel<<<blocks, threads>>>(user_item, pu, qi, bu, bi, gmean,
                                            out_pred, out_feat);
}

// round 15
// speedup vs baseline: 1.7116x; 1.0171x over previous
#include <cuda_runtime.h>
#include <cuda_bf16.h>
#include <cstdint>

// SVD recommender predict:
//   predict[b]  = clip(gm + bu[uid] + bi[iid] + dot(pu[uid], qi[iid]), 1, 5)
//   feat[b,:64] = pu[uid], feat[b,64:128] = qi[iid]
// d_out layout: [0:B) predict, [B : B+B*128) features row-major.
//
// 8 lanes per group, 2 elements per group (ILP=2):
//   - one int4 index load covers both elements' (uid,iid)
//   - 8 independent LDG.128 per thread, each warp-instruction covering
//     4 rows x one FULL 128B line (wavefront-optimal, zero waste)
//   - 8 STG.128 .cs full-line streaming stores
// MLP=8 gathers/thread behind a single index load.

#define N_FACTORS 64
#define BATCH     131072

__device__ __forceinline__ void stcs4(float4* p, float4 v) {
    asm volatile("st.global.cs.v4.f32 [%0], {%1,%2,%3,%4};"
                 :: "l"(p), "f"(v.x), "f"(v.y), "f"(v.z), "f"(v.w));
}

__global__ __launch_bounds__(256) void svd_predict_kernel(
    const int4*   __restrict__ user_item2,  // [BATCH/2] {uid0,iid0,uid1,iid1}
    const float4* __restrict__ pu,          // [N_USERS * 16] float4
    const float4* __restrict__ qi,          // [N_ITEMS * 16] float4
    const float*  __restrict__ bu,
    const float*  __restrict__ bi,
    const float*  __restrict__ gmean,
    float*        __restrict__ out_pred,    // [BATCH]
    float4*       __restrict__ out_feat)    // [BATCH * 32] float4
{
    const int tid   = blockIdx.x * blockDim.x + threadIdx.x;
    const int group = tid >> 3;         // handles elements 2g, 2g+1
    const int lane  = tid & 7;
    if (group >= BATCH / 2) return;

    const int4 ui = __ldg(user_item2 + group);   // uid0,iid0,uid1,iid1

    const float4* __restrict__ prow0 = pu + (size_t)ui.x * 16;
    const float4* __restrict__ qrow0 = qi + (size_t)ui.y * 16;
    const float4* __restrict__ prow1 = pu + (size_t)ui.z * 16;
    const float4* __restrict__ qrow1 = qi + (size_t)ui.w * 16;

    // 8 independent full-line LDG.128 per thread.
    const float4 p00 = __ldg(prow0 + lane);
    const float4 p01 = __ldg(prow0 + 8 + lane);
    const float4 q00 = __ldg(qrow0 + lane);
    const float4 q01 = __ldg(qrow0 + 8 + lane);
    const float4 p10 = __ldg(prow1 + lane);
    const float4 p11 = __ldg(prow1 + 8 + lane);
    const float4 q10 = __ldg(qrow1 + lane);
    const float4 q11 = __ldg(qrow1 + 8 + lane);

    float dot0 = p00.x * q00.x + p00.y * q00.y + p00.z * q00.z + p00.w * q00.w
               + p01.x * q01.x + p01.y * q01.y + p01.z * q01.z + p01.w * q01.w;
    float dot1 = p10.x * q10.x + p10.y * q10.y + p10.z * q10.z + p10.w * q10.w
               + p11.x * q11.x + p11.y * q11.y + p11.z * q11.z + p11.w * q11.w;

    #pragma unroll
    for (int off = 4; off > 0; off >>= 1) {
        dot0 += __shfl_xor_sync(0xffffffffu, dot0, off);
        dot1 += __shfl_xor_sync(0xffffffffu, dot1, off);
    }

    // Feature rows (32 float4 each), full-line streaming stores.
    float4* frow0 = out_feat + (size_t)(2 * group) * 32;
    float4* frow1 = frow0 + 32;
    stcs4(frow0 + lane,      p00);
    stcs4(frow0 + 8 + lane,  p01);
    stcs4(frow0 + 16 + lane, q00);
    stcs4(frow0 + 24 + lane, q01);
    stcs4(frow1 + lane,      p10);
    stcs4(frow1 + 8 + lane,  p11);
    stcs4(frow1 + 16 + lane, q10);
    stcs4(frow1 + 24 + lane, q11);

    // Two predict scalars, written by lanes 0 and 1 in parallel.
    if (lane == 0) {
        float pr = gmean[0] + __ldg(bu + ui.x) + __ldg(bi + ui.y) + dot0;
        pr = fminf(fmaxf(pr, 1.0f), 5.0f);
        __stcs(out_pred + 2 * group, pr);
    } else if (lane == 1) {
        float pr = gmean[0] + __ldg(bu + ui.z) + __ldg(bi + ui.w) + dot1;
        pr = fminf(fmaxf(pr, 1.0f), 5.0f);
        __stcs(out_pred + 2 * group + 1, pr);
    }
}

extern "C" void kernel_launch(void* const* d_in, const int* in_sizes, int n_in,
                              void* d_out, int out_size)
{
    const int4*   user_item2 = (const int4*)  d_in[0];
    const float4* pu         = (const float4*)d_in[1];
    const float4* qi         = (const float4*)d_in[2];
    const float*  bu         = (const float*) d_in[3];
    const float*  bi         = (const float*) d_in[4];
    const float*  gmean      = (const float*) d_in[5];

    float*  out_pred = (float*)d_out;
    float4* out_feat = (float4*)((float*)d_out + BATCH);

    // 8 threads per 2 elements: BATCH/2 groups
    const int threads = 256;
    const int blocks  = (BATCH / 2 * 8) / threads;   // 2048
    svd_predict_kernel<<<blocks, threads>>>(user_item2, pu, qi, bu, bi, gmean,
                                            out_pred, out_feat);
}